// round 3
// baseline (speedup 1.0000x reference)
#include <cuda_runtime.h>

static constexpr int Tn = 512;
static constexpr int Bn = 512;
static constexpr long BTn = (long)Bn * Tn;

// Scratch (device globals; allocation-free kernel_launch)
__device__ float g_xg[(size_t)512 * 512 * 288];   // max 4H = 288
__device__ float g_seqA[(size_t)512 * 512 * 64];  // e1 out / d1 out
__device__ float g_seqB[(size_t)512 * 512 * 32];  // e2 out

__device__ __forceinline__ float fsig(float x) {
    return __fdividef(1.0f, 1.0f + __expf(-x));
}

// ---- packed f32x2 helpers (Blackwell) ----
__device__ __forceinline__ unsigned long long pk2(float lo, float hi) {
    unsigned long long r;
    asm("mov.b64 %0, {%1, %2};" : "=l"(r) : "f"(lo), "f"(hi));
    return r;
}
__device__ __forceinline__ void upk2(unsigned long long v, float& lo, float& hi) {
    asm("mov.b64 {%0, %1}, %2;" : "=f"(lo), "=f"(hi) : "l"(v));
}
__device__ __forceinline__ unsigned long long ffma2(
    unsigned long long a, unsigned long long b, unsigned long long c) {
    unsigned long long d;
    asm("fma.rn.f32x2 %0, %1, %2, %3;" : "=l"(d) : "l"(a), "l"(b), "l"(c));
    return d;
}

// ---------------------------------------------------------------------------
// Input-projection GEMM. TPB = G/OPT threads; each thread owns OPT gate rows
// (g, g+TPB, ...) of Wih in packed regs, so each SMEM row load feeds OPT
// accumulators (FFMA:LDS ratio = 2*OPT).
// ---------------------------------------------------------------------------
template <int IN, int G, int OPT>
__global__ void __launch_bounds__(G / OPT) gemm_xg_kernel(
    const float* __restrict__ in, const float* __restrict__ Wih,
    const float* __restrict__ bih, const float* __restrict__ bhh,
    float* __restrict__ xg)
{
    constexpr int ROWS = 128;
    constexpr int TPB = G / OPT;
    __shared__ __align__(16) float sIn[ROWS * IN];

    const int g = threadIdx.x;
    const size_t row0 = (size_t)blockIdx.x * ROWS;

    {
        const float4* src = (const float4*)(in + row0 * IN);
        float4* dst = (float4*)sIn;
        constexpr int NV = ROWS * IN / 4;
        for (int i = g; i < NV; i += TPB) dst[i] = src[i];
    }

    unsigned long long w2[OPT][IN / 2];
    float bias[OPT];
#pragma unroll
    for (int o = 0; o < OPT; o++) {
        const unsigned long long* wp =
            (const unsigned long long*)(Wih + (size_t)(g + o * TPB) * IN);
#pragma unroll
        for (int i = 0; i < IN / 2; i++) w2[o][i] = wp[i];
        bias[o] = bih[g + o * TPB] + bhh[g + o * TPB];
    }

    __syncthreads();

    float* outp = xg + row0 * G + g;
#pragma unroll 1
    for (int r = 0; r < ROWS; r++) {
        unsigned long long acc[OPT];
#pragma unroll
        for (int o = 0; o < OPT; o++) acc[o] = pk2(bias[o], 0.0f);
        const ulonglong2* rp = (const ulonglong2*)(sIn + r * IN);
#pragma unroll
        for (int i = 0; i < IN / 4; i++) {
            ulonglong2 v = rp[i];
#pragma unroll
            for (int o = 0; o < OPT; o++) {
                acc[o] = ffma2(w2[o][2 * i + 0], v.x, acc[o]);
                acc[o] = ffma2(w2[o][2 * i + 1], v.y, acc[o]);
            }
        }
#pragma unroll
        for (int o = 0; o < OPT; o++) {
            float lo, hi;
            upk2(acc[o], lo, hi);
            outp[(size_t)r * G + o * TPB] = lo + hi;
        }
    }
}

// ---------------------------------------------------------------------------
// Recurrent scan, H=32: warp-synchronous, one warp per batch row, zero block
// barriers. Lane m owns all 4 gates of unit m (4 Whh rows in packed regs) and
// the cell state c[m]. h double-buffered in SMEM.
// ---------------------------------------------------------------------------
__global__ void __launch_bounds__(32) lstm_rec32_kernel(
    const float* __restrict__ xg, const float* __restrict__ Whh,
    float* __restrict__ hout)
{
    constexpr int H = 32, G4 = 128;
    __shared__ __align__(16) float h_sm[2][H];

    const int m = threadIdx.x;
    const int b = blockIdx.x;

    unsigned long long w2[4][H / 2];
#pragma unroll
    for (int g = 0; g < 4; g++) {
        const unsigned long long* wp =
            (const unsigned long long*)(Whh + (size_t)(g * H + m) * H);
#pragma unroll
        for (int k = 0; k < H / 2; k++) w2[g][k] = wp[k];
    }

    h_sm[0][m] = 0.0f;
    h_sm[1][m] = 0.0f;
    float c = 0.0f;

    const float* xgp = xg + (size_t)b * Tn * G4;
    float* hp = hout + (size_t)b * Tn * H + m;

    float xn[4];
#pragma unroll
    for (int g = 0; g < 4; g++) xn[g] = xgp[g * H + m];
    __syncwarp();

    for (int t = 0; t < Tn; t++) {
        unsigned long long acc[4];
#pragma unroll
        for (int g = 0; g < 4; g++) acc[g] = pk2(xn[g], 0.0f);

        if (t + 1 < Tn) {
#pragma unroll
            for (int g = 0; g < 4; g++)
                xn[g] = xgp[(size_t)(t + 1) * G4 + g * H + m];
        }

        const ulonglong2* hb = (const ulonglong2*)h_sm[t & 1];
#pragma unroll
        for (int k = 0; k < H / 4; k++) {
            ulonglong2 hv = hb[k];
#pragma unroll
            for (int g = 0; g < 4; g++) {
                acc[g] = ffma2(w2[g][2 * k + 0], hv.x, acc[g]);
                acc[g] = ffma2(w2[g][2 * k + 1], hv.y, acc[g]);
            }
        }

        float a[4];
#pragma unroll
        for (int g = 0; g < 4; g++) {
            float lo, hi;
            upk2(acc[g], lo, hi);
            a[g] = lo + hi;
        }
        const float iv = fsig(a[0]);
        const float fv = fsig(a[1]);
        const float gv = 2.0f * fsig(2.0f * a[2]) - 1.0f;  // tanh
        const float ov = fsig(a[3]);
        c = fv * c + iv * gv;
        const float h = ov * (2.0f * fsig(2.0f * c) - 1.0f);
        h_sm[(t + 1) & 1][m] = h;
        hp[(size_t)t * H] = h;
        __syncwarp();
    }
}

// ---------------------------------------------------------------------------
// Recurrent scan, quad scheme (H=64, 72): block = 4H threads = 1 batch row.
// Thread 4m+p owns gate p of unit m (one Whh row, H/2 ffma2/step). Butterfly
// shuffle within the quad exchanges activated gates -> register-local cell
// update, ONE barrier per step. h double-buffered in SMEM.
// ---------------------------------------------------------------------------
template <int H>
__global__ void __launch_bounds__(4 * H, 2) lstm_recq_kernel(
    const float* __restrict__ xg, const float* __restrict__ Whh,
    float* __restrict__ hout)
{
    constexpr int G4 = 4 * H;
    __shared__ __align__(16) float h_sm[2][H];

    const int tid = threadIdx.x;
    const int m = tid >> 2;
    const int p = tid & 3;
    const int b = blockIdx.x;

    unsigned long long w2[H / 2];
    {
        const unsigned long long* wp =
            (const unsigned long long*)(Whh + (size_t)(p * H + m) * H);
#pragma unroll
        for (int k = 0; k < H / 2; k++) w2[k] = wp[k];
    }

    if (p == 0) {
        h_sm[0][m] = 0.0f;
        h_sm[1][m] = 0.0f;
    }
    float c = 0.0f;

    const float* xgp = xg + (size_t)b * Tn * G4 + p * H + m;
    float* hp = hout + (size_t)b * Tn * H + m;

    float xn = xgp[0];
    __syncthreads();

    for (int t = 0; t < Tn; t++) {
        unsigned long long acc0 = pk2(xn, 0.0f);
        unsigned long long acc1 = pk2(0.0f, 0.0f);

        if (t + 1 < Tn) xn = xgp[(size_t)(t + 1) * G4];

        const ulonglong2* hb = (const ulonglong2*)h_sm[t & 1];
#pragma unroll
        for (int k = 0; k < H / 4; k++) {
            ulonglong2 hv = hb[k];
            acc0 = ffma2(w2[2 * k + 0], hv.x, acc0);
            acc1 = ffma2(w2[2 * k + 1], hv.y, acc1);
        }
        float l0, h0, l1, h1;
        upk2(acc0, l0, h0);
        upk2(acc1, l1, h1);
        float a = (l0 + h0) + (l1 + h1);

        // single-exp activation: gate 2 is tanh = 2*sig(2x)-1
        const bool isg = (p == 2);
        float xa = isg ? 2.0f * a : a;
        float s = fsig(xa);
        a = isg ? (2.0f * s - 1.0f) : s;

        // butterfly exchange of activated gates within the quad
        float x1 = __shfl_xor_sync(0xffffffffu, a, 1);
        float e0 = (p & 1) ? x1 : a;   // gate (p & ~1)
        float e1 = (p & 1) ? a : x1;   // gate (p | 1)
        float y0 = __shfl_xor_sync(0xffffffffu, e0, 2);
        float y1 = __shfl_xor_sync(0xffffffffu, e1, 2);
        float iv, fv, gv, ov;
        if (p < 2) { iv = e0; fv = e1; gv = y0; ov = y1; }
        else       { iv = y0; fv = y1; gv = e0; ov = e1; }

        c = fv * c + iv * gv;
        const float h = ov * (2.0f * fsig(2.0f * c) - 1.0f);
        if (p == 0) {
            h_sm[(t + 1) & 1][m] = h;
            hp[(size_t)t * H] = h;
        }
        __syncthreads();
    }
}

// ---------------------------------------------------------------------------
extern "C" void kernel_launch(void* const* d_in, const int* in_sizes, int n_in,
                              void* d_out, int out_size)
{
    (void)in_sizes; (void)n_in; (void)out_size;

    const float* x    = (const float*)d_in[0];
    const float* e1W  = (const float*)d_in[1];
    const float* e1U  = (const float*)d_in[2];
    const float* e1bi = (const float*)d_in[3];
    const float* e1bh = (const float*)d_in[4];
    const float* e2W  = (const float*)d_in[5];
    const float* e2U  = (const float*)d_in[6];
    const float* e2bi = (const float*)d_in[7];
    const float* e2bh = (const float*)d_in[8];
    const float* d1W  = (const float*)d_in[9];
    const float* d1U  = (const float*)d_in[10];
    const float* d1bi = (const float*)d_in[11];
    const float* d1bh = (const float*)d_in[12];
    const float* d2W  = (const float*)d_in[13];
    const float* d2U  = (const float*)d_in[14];
    const float* d2bi = (const float*)d_in[15];
    const float* d2bh = (const float*)d_in[16];
    float* out = (float*)d_out;

    float *xg = nullptr, *sa = nullptr, *sb = nullptr;
    cudaGetSymbolAddress((void**)&xg, g_xg);
    cudaGetSymbolAddress((void**)&sa, g_seqA);
    cudaGetSymbolAddress((void**)&sb, g_seqB);

    const int gemmGrid = (int)(BTn / 128);  // 2048

    // e1: 72 -> 64
    gemm_xg_kernel<72, 256, 2><<<gemmGrid, 128>>>(x, e1W, e1bi, e1bh, xg);
    lstm_recq_kernel<64><<<Bn, 256>>>(xg, e1U, sa);
    // e2: 64 -> 32
    gemm_xg_kernel<64, 128, 2><<<gemmGrid, 64>>>(sa, e2W, e2bi, e2bh, xg);
    lstm_rec32_kernel<<<Bn, 32>>>(xg, e2U, sb);
    // d1: 32 -> 64
    gemm_xg_kernel<32, 256, 2><<<gemmGrid, 128>>>(sb, d1W, d1bi, d1bh, xg);
    lstm_recq_kernel<64><<<Bn, 256>>>(xg, d1U, sa);
    // d2: 64 -> 72 (G=288 not divisible by 2 warps cleanly -> OPT=1)
    gemm_xg_kernel<64, 288, 1><<<gemmGrid, 288>>>(sa, d2W, d2bi, d2bh, xg);
    lstm_recq_kernel<72><<<Bn, 288>>>(xg, d2U, out);
}